// round 4
// baseline (speedup 1.0000x reference)
#include <cuda_runtime.h>
#include <stdint.h>

// HashGridEncoder: instant-NGP multiresolution hash grid encode.
// x: [N,3] f32; aabb: [3] f32; table: [16, 2^19, 2] f32. out: [N,32] f32.
// Levels 0..2 dense (res 16/32/64), 3..15 hashed.
// R4: 3-level gather batches (MLP=24 in flight) to saturate L1tex wavefront
// issue; occupancy intentionally traded for per-warp MLP (R3 lesson).

#define HG_NUM_LEVELS 16
#define HG_TABLE_SIZE (1u << 19)
#define HG_MASK (HG_TABLE_SIZE - 1u)
#define HG_PRIME_Y 2654435761u
#define HG_PRIME_Z 805459861u

struct LevelSetup {
    unsigned idx[8];
    float tx, ty, tz;
};

// l is compile-time constant in unrolled callers; dense/hashed branch folds.
__device__ __forceinline__ void level_setup(
    int l, float xn0, float xn1, float xn2, LevelSetup& s)
{
    const unsigned res = 16u << l;
    const float resf = (float)res;

    const float px = xn0 * resf;
    const float py = xn1 * resf;
    const float pz = xn2 * resf;
    const float fx = floorf(px);
    const float fy = floorf(py);
    const float fz = floorf(pz);
    s.tx = px - fx;
    s.ty = py - fy;
    s.tz = pz - fz;
    const unsigned cx = (unsigned)fx;
    const unsigned cy = (unsigned)fy;
    const unsigned cz = (unsigned)fz;

    if ((unsigned long long)(res + 1) * (res + 1) * (res + 1) <=
        (unsigned long long)HG_TABLE_SIZE) {
        const unsigned st = res + 1;
        const unsigned s2 = st * st;
        const unsigned base = cx + cy * st + cz * s2;
        s.idx[0] = base;           s.idx[1] = base + 1;
        s.idx[2] = base + st;      s.idx[3] = base + st + 1;
        s.idx[4] = base + s2;      s.idx[5] = base + s2 + 1;
        s.idx[6] = base + st + s2; s.idx[7] = base + st + s2 + 1;
    } else {
        const unsigned hy0 = cy * HG_PRIME_Y, hy1 = hy0 + HG_PRIME_Y;
        const unsigned hz0 = cz * HG_PRIME_Z, hz1 = hz0 + HG_PRIME_Z;
        const unsigned e00 = hy0 ^ hz0, e10 = hy1 ^ hz0;
        const unsigned e01 = hy0 ^ hz1, e11 = hy1 ^ hz1;
        const unsigned cx1 = cx + 1u;
        s.idx[0] = (cx  ^ e00) & HG_MASK;  s.idx[1] = (cx1 ^ e00) & HG_MASK;
        s.idx[2] = (cx  ^ e10) & HG_MASK;  s.idx[3] = (cx1 ^ e10) & HG_MASK;
        s.idx[4] = (cx  ^ e01) & HG_MASK;  s.idx[5] = (cx1 ^ e01) & HG_MASK;
        s.idx[6] = (cx  ^ e11) & HG_MASK;  s.idx[7] = (cx1 ^ e11) & HG_MASK;
    }
}

__device__ __forceinline__ void level_reduce(
    const LevelSetup& s, const float2 v[8], float& f0, float& f1)
{
    const float wx1 = s.tx, wx0 = 1.0f - s.tx;
    const float wy1 = s.ty, wy0 = 1.0f - s.ty;
    const float wz1 = s.tz, wz0 = 1.0f - s.tz;
    const float w00 = wy0 * wz0, w10 = wy1 * wz0;
    const float w01 = wy0 * wz1, w11 = wy1 * wz1;
    const float w000 = wx0 * w00, w100 = wx1 * w00;
    const float w010 = wx0 * w10, w110 = wx1 * w10;
    const float w001 = wx0 * w01, w101 = wx1 * w01;
    const float w011 = wx0 * w11, w111 = wx1 * w11;

    f0 = w000 * v[0].x + w100 * v[1].x + w010 * v[2].x + w110 * v[3].x +
         w001 * v[4].x + w101 * v[5].x + w011 * v[6].x + w111 * v[7].x;
    f1 = w000 * v[0].y + w100 * v[1].y + w010 * v[2].y + w110 * v[3].y +
         w001 * v[4].y + w101 * v[5].y + w011 * v[6].y + w111 * v[7].y;
}

// Gather+reduce a batch of CNT consecutive levels starting at L0.
// All CNT*8 loads are issued before any value is consumed (MLP = 8*CNT).
template <int L0, int CNT>
__device__ __forceinline__ void do_batch(
    const float2* __restrict__ tab,
    float xn0, float xn1, float xn2,
    float (&sline)[33])   // this thread's smem row: sbuf[warp][lane]
{
    LevelSetup s[CNT];
#pragma unroll
    for (int i = 0; i < CNT; ++i)
        level_setup(L0 + i, xn0, xn1, xn2, s[i]);

    float2 v[CNT][8];
#pragma unroll
    for (int i = 0; i < CNT; ++i) {
        const float2* __restrict__ tl = tab + (size_t)(L0 + i) * HG_TABLE_SIZE;
#pragma unroll
        for (int j = 0; j < 8; ++j)
            v[i][j] = __ldg(tl + s[i].idx[j]);
    }

#pragma unroll
    for (int i = 0; i < CNT; ++i) {
        float f0, f1;
        level_reduce(s[i], v[i], f0, f1);
        sline[2 * (L0 + i)]     = f0;
        sline[2 * (L0 + i) + 1] = f1;
    }
}

__global__ __launch_bounds__(128) void hashgrid_encode_kernel(
    const float* __restrict__ x,
    const float* __restrict__ aabb,
    const float* __restrict__ table,
    float* __restrict__ out,
    int n)
{
    // per-warp transpose tile: 32 points x 32 feats, padded -> conflict-free
    __shared__ float sbuf[4][32][33];

    const int tid  = blockIdx.x * blockDim.x + threadIdx.x;
    const int warp = threadIdx.x >> 5;
    const int lane = threadIdx.x & 31;
    const bool active = (tid < n);
    const int pi = active ? tid : 0;   // clamp so gathers stay in-bounds

    const float a0 = __ldg(aabb + 0);
    const float a1 = __ldg(aabb + 1);
    const float a2 = __ldg(aabb + 2);

    const float px_in = __ldg(x + 3 * (size_t)pi + 0);
    const float py_in = __ldg(x + 3 * (size_t)pi + 1);
    const float pz_in = __ldg(x + 3 * (size_t)pi + 2);

    // normalize_aabb then bound (-1,1) -> [0,1]; matches reference fp32 order
    const float xn0 = (px_in / a0 + 1.0f) * 0.5f;
    const float xn1 = (py_in / a1 + 1.0f) * 0.5f;
    const float xn2 = (pz_in / a2 + 1.0f) * 0.5f;

    const float2* __restrict__ tab = (const float2*)table;
    float (&sline)[33] = sbuf[warp][lane];

    do_batch<0,  3>(tab, xn0, xn1, xn2, sline);
    do_batch<3,  3>(tab, xn0, xn1, xn2, sline);
    do_batch<6,  3>(tab, xn0, xn1, xn2, sline);
    do_batch<9,  3>(tab, xn0, xn1, xn2, sline);
    do_batch<12, 2>(tab, xn0, xn1, xn2, sline);
    do_batch<14, 2>(tab, xn0, xn1, xn2, sline);

    __syncwarp();

    // coalesced transposed store: each warp writes 32 contiguous 128B rows
    const int base_pt = blockIdx.x * blockDim.x + warp * 32;
#pragma unroll
    for (int r = 0; r < 32; ++r) {
        const int pt = base_pt + r;
        if (pt < n) {
            out[(size_t)pt * 32 + lane] = sbuf[warp][r][lane];
        }
    }
}

extern "C" void kernel_launch(void* const* d_in, const int* in_sizes, int n_in,
                              void* d_out, int out_size) {
    const float* x     = (const float*)d_in[0];   // [N,3]
    const float* aabb  = (const float*)d_in[1];   // [3]
    const float* table = (const float*)d_in[2];   // [16, 2^19, 2]
    float* out = (float*)d_out;                   // [N, 32]

    const int n = in_sizes[0] / 3;
    const int threads = 128;
    const int blocks = (n + threads - 1) / threads;
    hashgrid_encode_kernel<<<blocks, threads>>>(x, aabb, table, out, n);
}

// round 5
// speedup vs baseline: 2.3380x; 2.3380x over previous
#include <cuda_runtime.h>
#include <stdint.h>

// HashGridEncoder: instant-NGP multiresolution hash grid encode.
// x: [N,3] f32; aabb: [3] f32; table: [16, 2^19, 2] f32. out: [N,32] f32.
// Levels 0..2 dense (res 16/32/64), 3..15 hashed.
// R5: R3 two-half skeleton + asm-volatile gathers so ptxas CANNOT sink the
// load batch (R2/R4 failure mode); batch raised to 4 levels (MLP=32).

#define HG_NUM_LEVELS 16
#define HG_TABLE_SIZE (1u << 19)
#define HG_MASK (HG_TABLE_SIZE - 1u)
#define HG_PRIME_Y 2654435761u
#define HG_PRIME_Z 805459861u

struct LevelSetup {
    unsigned idx[8];
    float tx, ty, tz;
};

// l is compile-time constant in unrolled callers; dense/hashed branch folds.
__device__ __forceinline__ void level_setup(
    int l, float xn0, float xn1, float xn2, LevelSetup& s)
{
    const unsigned res = 16u << l;
    const float resf = (float)res;

    const float px = xn0 * resf;
    const float py = xn1 * resf;
    const float pz = xn2 * resf;
    const float fx = floorf(px);
    const float fy = floorf(py);
    const float fz = floorf(pz);
    s.tx = px - fx;
    s.ty = py - fy;
    s.tz = pz - fz;
    const unsigned cx = (unsigned)fx;
    const unsigned cy = (unsigned)fy;
    const unsigned cz = (unsigned)fz;

    if ((unsigned long long)(res + 1) * (res + 1) * (res + 1) <=
        (unsigned long long)HG_TABLE_SIZE) {
        const unsigned st = res + 1;
        const unsigned s2 = st * st;
        const unsigned base = cx + cy * st + cz * s2;
        s.idx[0] = base;           s.idx[1] = base + 1;
        s.idx[2] = base + st;      s.idx[3] = base + st + 1;
        s.idx[4] = base + s2;      s.idx[5] = base + s2 + 1;
        s.idx[6] = base + st + s2; s.idx[7] = base + st + s2 + 1;
    } else {
        const unsigned hy0 = cy * HG_PRIME_Y, hy1 = hy0 + HG_PRIME_Y;
        const unsigned hz0 = cz * HG_PRIME_Z, hz1 = hz0 + HG_PRIME_Z;
        const unsigned e00 = hy0 ^ hz0, e10 = hy1 ^ hz0;
        const unsigned e01 = hy0 ^ hz1, e11 = hy1 ^ hz1;
        const unsigned cx1 = cx + 1u;
        s.idx[0] = (cx  ^ e00) & HG_MASK;  s.idx[1] = (cx1 ^ e00) & HG_MASK;
        s.idx[2] = (cx  ^ e10) & HG_MASK;  s.idx[3] = (cx1 ^ e10) & HG_MASK;
        s.idx[4] = (cx  ^ e01) & HG_MASK;  s.idx[5] = (cx1 ^ e01) & HG_MASK;
        s.idx[6] = (cx  ^ e11) & HG_MASK;  s.idx[7] = (cx1 ^ e11) & HG_MASK;
    }
}

// Gather + trilerp CNT consecutive levels starting at L0.
// Loads are asm volatile -> issued back-to-back in program order BEFORE any
// consumer; guaranteed MLP = 8*CNT regardless of ptxas heuristics.
template <int L0, int CNT>
__device__ __forceinline__ void gather_levels(
    const float2* __restrict__ tab,
    float xn0, float xn1, float xn2,
    float* __restrict__ sline,   // this thread's smem row (17-wide)
    int colbase)
{
    LevelSetup s[CNT];
#pragma unroll
    for (int i = 0; i < CNT; ++i)
        level_setup(L0 + i, xn0, xn1, xn2, s[i]);

    float vx[CNT][8], vy[CNT][8];
#pragma unroll
    for (int i = 0; i < CNT; ++i) {
        const float2* __restrict__ tl = tab + (size_t)(L0 + i) * HG_TABLE_SIZE;
#pragma unroll
        for (int j = 0; j < 8; ++j) {
            asm volatile("ld.global.nc.v2.f32 {%0, %1}, [%2];"
                         : "=f"(vx[i][j]), "=f"(vy[i][j])
                         : "l"(tl + s[i].idx[j]));
        }
    }

#pragma unroll
    for (int i = 0; i < CNT; ++i) {
        const float wx1 = s[i].tx, wx0 = 1.0f - s[i].tx;
        const float wy1 = s[i].ty, wy0 = 1.0f - s[i].ty;
        const float wz1 = s[i].tz, wz0 = 1.0f - s[i].tz;
        const float w00 = wy0 * wz0, w10 = wy1 * wz0;
        const float w01 = wy0 * wz1, w11 = wy1 * wz1;
        const float w000 = wx0 * w00, w100 = wx1 * w00;
        const float w010 = wx0 * w10, w110 = wx1 * w10;
        const float w001 = wx0 * w01, w101 = wx1 * w01;
        const float w011 = wx0 * w11, w111 = wx1 * w11;

        const float f0 =
            w000 * vx[i][0] + w100 * vx[i][1] + w010 * vx[i][2] +
            w110 * vx[i][3] + w001 * vx[i][4] + w101 * vx[i][5] +
            w011 * vx[i][6] + w111 * vx[i][7];
        const float f1 =
            w000 * vy[i][0] + w100 * vy[i][1] + w010 * vy[i][2] +
            w110 * vy[i][3] + w001 * vy[i][4] + w101 * vy[i][5] +
            w011 * vy[i][6] + w111 * vy[i][7];

        sline[colbase + 2 * i]     = f0;
        sline[colbase + 2 * i + 1] = f1;
    }
}

__global__ __launch_bounds__(128) void hashgrid_encode_kernel(
    const float* __restrict__ x,
    const float* __restrict__ aabb,
    const float* __restrict__ table,
    float* __restrict__ out,
    int n)
{
    // per-warp HALF tile: 32 points x 16 feats (levels 0-7, reused for 8-15)
    __shared__ float sbuf[4][32][17];

    const int tid  = blockIdx.x * blockDim.x + threadIdx.x;
    const int warp = threadIdx.x >> 5;
    const int lane = threadIdx.x & 31;
    const bool active = (tid < n);
    const int pi = active ? tid : 0;   // clamp so gathers stay in-bounds

    const float a0 = __ldg(aabb + 0);
    const float a1 = __ldg(aabb + 1);
    const float a2 = __ldg(aabb + 2);

    const float px_in = __ldg(x + 3 * (size_t)pi + 0);
    const float py_in = __ldg(x + 3 * (size_t)pi + 1);
    const float pz_in = __ldg(x + 3 * (size_t)pi + 2);

    // normalize_aabb then bound (-1,1) -> [0,1]; matches reference fp32 order
    const float xn0 = (px_in / a0 + 1.0f) * 0.5f;
    const float xn1 = (py_in / a1 + 1.0f) * 0.5f;
    const float xn2 = (pz_in / a2 + 1.0f) * 0.5f;

    const float2* __restrict__ tab = (const float2*)table;
    float* sline = &sbuf[warp][lane][0];
    const int base_pt = blockIdx.x * blockDim.x + warp * 32;

    // ---- half 0: levels 0..7 ----
    gather_levels<0, 4>(tab, xn0, xn1, xn2, sline, 0);
    gather_levels<4, 4>(tab, xn0, xn1, xn2, sline, 8);
    __syncwarp();
#pragma unroll
    for (int rr = 0; rr < 16; ++rr) {
        const int r = 2 * rr + (lane >> 4);
        const int c = lane & 15;
        const int pt = base_pt + r;
        if (pt < n) out[(size_t)pt * 32 + c] = sbuf[warp][r][c];
    }
    __syncwarp();

    // ---- half 1: levels 8..15 ----
    gather_levels<8, 4>(tab, xn0, xn1, xn2, sline, 0);
    gather_levels<12, 4>(tab, xn0, xn1, xn2, sline, 8);
    __syncwarp();
#pragma unroll
    for (int rr = 0; rr < 16; ++rr) {
        const int r = 2 * rr + (lane >> 4);
        const int c = lane & 15;
        const int pt = base_pt + r;
        if (pt < n) out[(size_t)pt * 32 + 16 + c] = sbuf[warp][r][c];
    }
}

extern "C" void kernel_launch(void* const* d_in, const int* in_sizes, int n_in,
                              void* d_out, int out_size) {
    const float* x     = (const float*)d_in[0];   // [N,3]
    const float* aabb  = (const float*)d_in[1];   // [3]
    const float* table = (const float*)d_in[2];   // [16, 2^19, 2]
    float* out = (float*)d_out;                   // [N, 32]

    const int n = in_sizes[0] / 3;
    const int threads = 128;
    const int blocks = (n + threads - 1) / threads;
    hashgrid_encode_kernel<<<blocks, threads>>>(x, aabb, table, out, n);
}

// round 6
// speedup vs baseline: 2.3382x; 1.0001x over previous
#include <cuda_runtime.h>
#include <stdint.h>

// HashGridEncoder: instant-NGP multiresolution hash grid encode.
// x: [N,3] f32; aabb: [3] f32; table: [16, 2^19, 2] f32. out: [N,32] f32.
// Levels 0..2 dense (res 16/32/64), 3..15 hashed.
// R6: depth-2 software pipeline of 2-level gather batches (asm volatile) so
// every warp keeps >=16 gathers outstanding through reduce AND store phases.

#define HG_TABLE_SIZE (1u << 19)
#define HG_MASK (HG_TABLE_SIZE - 1u)
#define HG_PRIME_Y 2654435761u
#define HG_PRIME_Z 805459861u

struct LevelSetup {
    unsigned idx[8];
    float tx, ty, tz;
};

// l is compile-time constant in unrolled callers; dense/hashed branch folds.
__device__ __forceinline__ void level_setup(
    int l, float xn0, float xn1, float xn2, LevelSetup& s)
{
    const unsigned res = 16u << l;
    const float resf = (float)res;

    const float px = xn0 * resf;
    const float py = xn1 * resf;
    const float pz = xn2 * resf;
    const float fx = floorf(px);
    const float fy = floorf(py);
    const float fz = floorf(pz);
    s.tx = px - fx;
    s.ty = py - fy;
    s.tz = pz - fz;
    const unsigned cx = (unsigned)fx;
    const unsigned cy = (unsigned)fy;
    const unsigned cz = (unsigned)fz;

    if ((unsigned long long)(res + 1) * (res + 1) * (res + 1) <=
        (unsigned long long)HG_TABLE_SIZE) {
        const unsigned st = res + 1;
        const unsigned s2 = st * st;
        const unsigned base = cx + cy * st + cz * s2;
        s.idx[0] = base;           s.idx[1] = base + 1;
        s.idx[2] = base + st;      s.idx[3] = base + st + 1;
        s.idx[4] = base + s2;      s.idx[5] = base + s2 + 1;
        s.idx[6] = base + st + s2; s.idx[7] = base + st + s2 + 1;
    } else {
        const unsigned hy0 = cy * HG_PRIME_Y, hy1 = hy0 + HG_PRIME_Y;
        const unsigned hz0 = cz * HG_PRIME_Z, hz1 = hz0 + HG_PRIME_Z;
        const unsigned e00 = hy0 ^ hz0, e10 = hy1 ^ hz0;
        const unsigned e01 = hy0 ^ hz1, e11 = hy1 ^ hz1;
        const unsigned cx1 = cx + 1u;
        s.idx[0] = (cx  ^ e00) & HG_MASK;  s.idx[1] = (cx1 ^ e00) & HG_MASK;
        s.idx[2] = (cx  ^ e10) & HG_MASK;  s.idx[3] = (cx1 ^ e10) & HG_MASK;
        s.idx[4] = (cx  ^ e01) & HG_MASK;  s.idx[5] = (cx1 ^ e01) & HG_MASK;
        s.idx[6] = (cx  ^ e11) & HG_MASK;  s.idx[7] = (cx1 ^ e11) & HG_MASK;
    }
}

// Ping-pong buffer holding 2 levels' setups + gathered values (16 loads).
struct Batch2 {
    LevelSetup s[2];
    float vx[2][8];
    float vy[2][8];
};

// Issue both levels' 16 gathers via volatile asm: program-order issue,
// cannot be sunk past consumers by ptxas.
template <int L0>
__device__ __forceinline__ void issue_batch(
    const float2* __restrict__ tab,
    float xn0, float xn1, float xn2, Batch2& b)
{
    level_setup(L0,     xn0, xn1, xn2, b.s[0]);
    level_setup(L0 + 1, xn0, xn1, xn2, b.s[1]);
#pragma unroll
    for (int i = 0; i < 2; ++i) {
        const float2* __restrict__ tl =
            tab + (size_t)(L0 + i) * HG_TABLE_SIZE;
#pragma unroll
        for (int j = 0; j < 8; ++j) {
            asm volatile("ld.global.nc.v2.f32 {%0, %1}, [%2];"
                         : "=f"(b.vx[i][j]), "=f"(b.vy[i][j])
                         : "l"(tl + b.s[i].idx[j]));
        }
    }
}

// Trilinear reduce of a 2-level batch into the half-tile smem row.
// Column base for level l within the 16-wide half tile: (2*l) & 15.
template <int L0>
__device__ __forceinline__ void reduce_batch(
    const Batch2& b, float* __restrict__ sline)
{
    const int colbase = (2 * L0) & 15;
#pragma unroll
    for (int i = 0; i < 2; ++i) {
        const float wx1 = b.s[i].tx, wx0 = 1.0f - b.s[i].tx;
        const float wy1 = b.s[i].ty, wy0 = 1.0f - b.s[i].ty;
        const float wz1 = b.s[i].tz, wz0 = 1.0f - b.s[i].tz;
        const float w00 = wy0 * wz0, w10 = wy1 * wz0;
        const float w01 = wy0 * wz1, w11 = wy1 * wz1;
        const float w000 = wx0 * w00, w100 = wx1 * w00;
        const float w010 = wx0 * w10, w110 = wx1 * w10;
        const float w001 = wx0 * w01, w101 = wx1 * w01;
        const float w011 = wx0 * w11, w111 = wx1 * w11;

        const float f0 =
            w000 * b.vx[i][0] + w100 * b.vx[i][1] + w010 * b.vx[i][2] +
            w110 * b.vx[i][3] + w001 * b.vx[i][4] + w101 * b.vx[i][5] +
            w011 * b.vx[i][6] + w111 * b.vx[i][7];
        const float f1 =
            w000 * b.vy[i][0] + w100 * b.vy[i][1] + w010 * b.vy[i][2] +
            w110 * b.vy[i][3] + w001 * b.vy[i][4] + w101 * b.vy[i][5] +
            w011 * b.vy[i][6] + w111 * b.vy[i][7];

        sline[colbase + 2 * i]     = f0;
        sline[colbase + 2 * i + 1] = f1;
    }
}

__global__ __launch_bounds__(128) void hashgrid_encode_kernel(
    const float* __restrict__ x,
    const float* __restrict__ aabb,
    const float* __restrict__ table,
    float* __restrict__ out,
    int n)
{
    // per-warp HALF tile: 32 points x 16 feats (levels 0-7, reused for 8-15)
    __shared__ float sbuf[4][32][17];

    const int tid  = blockIdx.x * blockDim.x + threadIdx.x;
    const int warp = threadIdx.x >> 5;
    const int lane = threadIdx.x & 31;
    const bool active = (tid < n);
    const int pi = active ? tid : 0;   // clamp so gathers stay in-bounds

    const float a0 = __ldg(aabb + 0);
    const float a1 = __ldg(aabb + 1);
    const float a2 = __ldg(aabb + 2);

    const float px_in = __ldg(x + 3 * (size_t)pi + 0);
    const float py_in = __ldg(x + 3 * (size_t)pi + 1);
    const float pz_in = __ldg(x + 3 * (size_t)pi + 2);

    // normalize_aabb then bound (-1,1) -> [0,1]; matches reference fp32 order
    const float xn0 = (px_in / a0 + 1.0f) * 0.5f;
    const float xn1 = (py_in / a1 + 1.0f) * 0.5f;
    const float xn2 = (pz_in / a2 + 1.0f) * 0.5f;

    const float2* __restrict__ tab = (const float2*)table;
    float* sline = &sbuf[warp][lane][0];
    const int base_pt = blockIdx.x * blockDim.x + warp * 32;

    Batch2 b0, b1;

    // ---- pipelined levels 0..7 (half 0) ----
    issue_batch<0>(tab, xn0, xn1, xn2, b0);
    issue_batch<2>(tab, xn0, xn1, xn2, b1);
    reduce_batch<0>(b0, sline);
    issue_batch<4>(tab, xn0, xn1, xn2, b0);
    reduce_batch<2>(b1, sline);
    issue_batch<6>(tab, xn0, xn1, xn2, b1);
    reduce_batch<4>(b0, sline);
    issue_batch<8>(tab, xn0, xn1, xn2, b0);   // prefetch half 1 across store
    reduce_batch<6>(b1, sline);

    __syncwarp();
#pragma unroll
    for (int rr = 0; rr < 16; ++rr) {
        const int r = 2 * rr + (lane >> 4);
        const int c = lane & 15;
        const int pt = base_pt + r;
        if (pt < n) out[(size_t)pt * 32 + c] = sbuf[warp][r][c];
    }
    __syncwarp();

    // ---- pipelined levels 8..15 (half 1) ----
    issue_batch<10>(tab, xn0, xn1, xn2, b1);
    reduce_batch<8>(b0, sline);
    issue_batch<12>(tab, xn0, xn1, xn2, b0);
    reduce_batch<10>(b1, sline);
    issue_batch<14>(tab, xn0, xn1, xn2, b1);
    reduce_batch<12>(b0, sline);
    reduce_batch<14>(b1, sline);

    __syncwarp();
#pragma unroll
    for (int rr = 0; rr < 16; ++rr) {
        const int r = 2 * rr + (lane >> 4);
        const int c = lane & 15;
        const int pt = base_pt + r;
        if (pt < n) out[(size_t)pt * 32 + 16 + c] = sbuf[warp][r][c];
    }
}

extern "C" void kernel_launch(void* const* d_in, const int* in_sizes, int n_in,
                              void* d_out, int out_size) {
    const float* x     = (const float*)d_in[0];   // [N,3]
    const float* aabb  = (const float*)d_in[1];   // [3]
    const float* table = (const float*)d_in[2];   // [16, 2^19, 2]
    float* out = (float*)d_out;                   // [N, 32]

    const int n = in_sizes[0] / 3;
    const int threads = 128;
    const int blocks = (n + threads - 1) / threads;
    hashgrid_encode_kernel<<<blocks, threads>>>(x, aabb, table, out, n);
}